// round 8
// baseline (speedup 1.0000x reference)
#include <cuda_runtime.h>
#include <cstdint>

// PWC-Net correlation, B=8, C=128, H=112, W=192, 81 disps (dy,dx in [-4,4]).
// Round 8: h-pair register blocking. Each block computes output rows h0,h0+1.
// 10 dy-row groups x 48 pixel-quads = 480 threads. A second row r feeds BOTH
// (h0, dy=r-h0) and (h0+1, dy=r-h0-1) accumulator sets from the same E
// operands -> second-row load volume per output row drops 1.5x.

#define B_ 8
#define C_ 128
#define H_ 112
#define W_ 192
#define HW_ (H_ * W_)
#define HP_ 120     // H + 8
#define WP_ 224     // 896 B rows (128B-aligned); left pad 4, right pad 28
#define HWP_ (HP_ * WP_)

typedef unsigned long long ull;

// fully padded copy of `second`: [B, C, HP, WP], 110.1 MB
__device__ __align__(16) float g_spad[B_ * C_ * HWP_];

__device__ __forceinline__ void fma2(ull& acc, ull a, ull b) {
    asm("fma.rn.f32x2 %0, %1, %2, %0;" : "+l"(acc) : "l"(a), "l"(b));
}
__device__ __forceinline__ void mul2(ull& v, ull s) {
    asm("mul.rn.f32x2 %0, %0, %1;" : "+l"(v) : "l"(s));
}
__device__ __forceinline__ ull pack_hl(ull a, ull b) {   // (a.hi, b.lo)
    return (a >> 32) | (b << 32);
}
__device__ __forceinline__ ull swap2(ull a) {            // (a.hi, a.lo)
    return (a >> 32) | (a << 32);
}
__device__ __forceinline__ ull lo_(float x, float y) {
    return (ull)__float_as_uint(x) | ((ull)__float_as_uint(y) << 32);
}

__global__ __launch_bounds__(256)
void pad_kernel(const float* __restrict__ second) {
    int i = blockIdx.x * blockDim.x + threadIdx.x;
    const int total = B_ * C_ * HP_ * (WP_ / 4);
    if (i >= total) return;
    int q    = i % (WP_ / 4);            // 0..55
    int rest = i / (WP_ / 4);
    int y    = rest % HP_;
    int bc   = rest / HP_;
    int ys   = y - 4;
    float4 v = make_float4(0.f, 0.f, 0.f, 0.f);
    if (q >= 1 && q <= 48 && ys >= 0 && ys < H_) {
        v = *reinterpret_cast<const float4*>(
            second + ((size_t)bc * H_ + ys) * W_ + (4 * q - 4));
    }
    reinterpret_cast<float4*>(g_spad)[i] = v;
}

__global__ __launch_bounds__(480, 1)
void corr81_kernel(const float* __restrict__ first,
                   float* __restrict__ out) {
    const int h0  = 2 * blockIdx.x;    // output rows h0, h0+1
    const int b   = blockIdx.y;
    const int tid = threadIdx.x;       // 0..479
    const int pq  = tid % 48;
    const int g   = tid / 48;          // 0..9: second padded row = h0 + g
    const int w0  = 4 * pq;

    // set 0: output row h0, dy_pad = g      (valid g<=8)
    // set 1: output row h0+1, dy_pad = g-1  (valid g>=1)
    ull e0[5], a0[5], f0e[5], f0a[5];  // h0: pair a (e0,a0), pair b (f0e,f0a)
    ull e1[5], a1[5], f1e[5], f1a[5];  // h1
#pragma unroll
    for (int m = 0; m < 5; m++) {
        e0[m]=0; a0[m]=0; f0e[m]=0; f0a[m]=0;
        e1[m]=0; a1[m]=0; f1e[m]=0; f1a[m]=0;
    }

    const float4* srow = reinterpret_cast<const float4*>(
        g_spad + ((size_t)(b * C_) * HP_ + (h0 + g)) * WP_ + w0);
    const float4* fp0 = reinterpret_cast<const float4*>(
        first + ((size_t)(b * C_) * H_ + h0) * W_ + w0);
    const float4* fp1 = fp0 + W_ / 4;   // row h0+1

    for (int c = 0; c < C_; c++) {
        const float4 F0 = *fp0;  fp0 += HW_ / 4;
        const float4 F1 = *fp1;  fp1 += HW_ / 4;
        const float4 V0 = srow[0];
        const float4 V1 = srow[1];
        const float4 V2 = srow[2];
        srow += HWP_ / 4;

        const ull E0 = lo_(V0.x, V0.y);
        const ull E1 = lo_(V0.z, V0.w);
        const ull E2 = lo_(V1.x, V1.y);
        const ull E3 = lo_(V1.z, V1.w);
        const ull E4 = lo_(V2.x, V2.y);
        const ull E5 = lo_(V2.z, V2.w);

        const ull p0a = lo_(F0.x, F0.y), p0b = lo_(F0.z, F0.w);
        const ull s0a = swap2(p0a),      s0b = swap2(p0b);
        const ull p1a = lo_(F1.x, F1.y), p1b = lo_(F1.z, F1.w);
        const ull s1a = swap2(p1a),      s1b = swap2(p1b);

        // h0: pair a uses E0..E4, pair b uses E1..E5
        fma2(e0[0], p0a, E0);  fma2(a0[0], s0a, E0);
        fma2(e0[1], p0a, E1);  fma2(a0[1], s0a, E1);
        fma2(e0[2], p0a, E2);  fma2(a0[2], s0a, E2);
        fma2(e0[3], p0a, E3);  fma2(a0[3], s0a, E3);
        fma2(e0[4], p0a, E4);  fma2(a0[4], s0a, E4);
        fma2(f0e[0], p0b, E1); fma2(f0a[0], s0b, E1);
        fma2(f0e[1], p0b, E2); fma2(f0a[1], s0b, E2);
        fma2(f0e[2], p0b, E3); fma2(f0a[2], s0b, E3);
        fma2(f0e[3], p0b, E4); fma2(f0a[3], s0b, E4);
        fma2(f0e[4], p0b, E5); fma2(f0a[4], s0b, E5);

        // h1: same E operands
        fma2(e1[0], p1a, E0);  fma2(a1[0], s1a, E0);
        fma2(e1[1], p1a, E1);  fma2(a1[1], s1a, E1);
        fma2(e1[2], p1a, E2);  fma2(a1[2], s1a, E2);
        fma2(e1[3], p1a, E3);  fma2(a1[3], s1a, E3);
        fma2(e1[4], p1a, E4);  fma2(a1[4], s1a, E4);
        fma2(f1e[0], p1b, E1); fma2(f1a[0], s1b, E1);
        fma2(f1e[1], p1b, E2); fma2(f1a[1], s1b, E2);
        fma2(f1e[2], p1b, E3); fma2(f1a[2], s1b, E3);
        fma2(f1e[3], p1b, E4); fma2(f1a[3], s1b, E4);
        fma2(f1e[4], p1b, E5); fma2(f1a[4], s1b, E5);
    }

    const unsigned sb = __float_as_uint(1.0f / (float)C_);
    const ull scale2 = (ull)sb | ((ull)sb << 32);

    if (g <= 8) {   // store set 0: channel g*9+dx at row h0
        float* od = out + (((size_t)(b * 81 + g * 9)) * H_ + h0) * W_ + w0;
#pragma unroll
        for (int m = 0; m < 5; m++) {
            ull va = e0[m];  mul2(va, scale2);
            ull vb = f0e[m]; mul2(vb, scale2);
            ulonglong2 pk; pk.x = va; pk.y = vb;
            *reinterpret_cast<ulonglong2*>(od + (size_t)(2 * m) * HW_) = pk;
        }
#pragma unroll
        for (int m = 0; m < 4; m++) {
            ull va = pack_hl(a0[m], a0[m + 1]); mul2(va, scale2);
            ull vb = pack_hl(f0a[m], f0a[m + 1]); mul2(vb, scale2);
            ulonglong2 pk; pk.x = va; pk.y = vb;
            *reinterpret_cast<ulonglong2*>(od + (size_t)(2 * m + 1) * HW_) = pk;
        }
    }
    if (g >= 1) {   // store set 1: channel (g-1)*9+dx at row h0+1
        float* od = out + (((size_t)(b * 81 + (g - 1) * 9)) * H_ + (h0 + 1)) * W_ + w0;
#pragma unroll
        for (int m = 0; m < 5; m++) {
            ull va = e1[m];  mul2(va, scale2);
            ull vb = f1e[m]; mul2(vb, scale2);
            ulonglong2 pk; pk.x = va; pk.y = vb;
            *reinterpret_cast<ulonglong2*>(od + (size_t)(2 * m) * HW_) = pk;
        }
#pragma unroll
        for (int m = 0; m < 4; m++) {
            ull va = pack_hl(a1[m], a1[m + 1]); mul2(va, scale2);
            ull vb = pack_hl(f1a[m], f1a[m + 1]); mul2(vb, scale2);
            ulonglong2 pk; pk.x = va; pk.y = vb;
            *reinterpret_cast<ulonglong2*>(od + (size_t)(2 * m + 1) * HW_) = pk;
        }
    }
}

extern "C" void kernel_launch(void* const* d_in, const int* in_sizes, int n_in,
                              void* d_out, int out_size) {
    const float* first  = (const float*)d_in[0];
    const float* second = (const float*)d_in[1];
    float* out = (float*)d_out;

    const int pad_elems = B_ * C_ * HP_ * (WP_ / 4);
    pad_kernel<<<(pad_elems + 255) / 256, 256>>>(second);

    dim3 grid(H_ / 2, B_);   // (56, 8) h-pairs
    corr81_kernel<<<grid, 480>>>(first, out);
}

// round 9
// speedup vs baseline: 1.4504x; 1.4504x over previous
#include <cuda_runtime.h>
#include <cstdint>

// PWC-Net correlation, B=8, C=128, H=112, W=192, 81 disps (dy,dx in [-4,4]).
// Round 9: R8 h-pair register blocking + software-pipelined (double-buffered)
// V loads: issue channel c+1's second-row loads before channel c's FMA block,
// hiding the L2/queue latency inside the warp (occupancy is reg-capped at 1 CTA).

#define B_ 8
#define C_ 128
#define H_ 112
#define W_ 192
#define HW_ (H_ * W_)
#define HP_ 120     // H + 8
#define WP_ 224     // 896 B rows (128B multiple); left pad 4, right pad 28
#define HWP_ (HP_ * WP_)

typedef unsigned long long ull;

// fully padded copy of `second`: [B, C, HP, WP], 110.1 MB
__device__ __align__(16) float g_spad[B_ * C_ * HWP_];

__device__ __forceinline__ void fma2(ull& acc, ull a, ull b) {
    asm("fma.rn.f32x2 %0, %1, %2, %0;" : "+l"(acc) : "l"(a), "l"(b));
}
__device__ __forceinline__ void mul2(ull& v, ull s) {
    asm("mul.rn.f32x2 %0, %0, %1;" : "+l"(v) : "l"(s));
}
__device__ __forceinline__ ull pack_hl(ull a, ull b) {   // (a.hi, b.lo)
    return (a >> 32) | (b << 32);
}
__device__ __forceinline__ ull swap2(ull a) {            // (a.hi, a.lo)
    return (a >> 32) | (a << 32);
}
__device__ __forceinline__ ull lo_(float x, float y) {
    return (ull)__float_as_uint(x) | ((ull)__float_as_uint(y) << 32);
}

__global__ __launch_bounds__(256)
void pad_kernel(const float* __restrict__ second) {
    int i = blockIdx.x * blockDim.x + threadIdx.x;
    const int total = B_ * C_ * HP_ * (WP_ / 4);
    if (i >= total) return;
    int q    = i % (WP_ / 4);            // 0..55
    int rest = i / (WP_ / 4);
    int y    = rest % HP_;
    int bc   = rest / HP_;
    int ys   = y - 4;
    float4 v = make_float4(0.f, 0.f, 0.f, 0.f);
    if (q >= 1 && q <= 48 && ys >= 0 && ys < H_) {
        v = *reinterpret_cast<const float4*>(
            second + ((size_t)bc * H_ + ys) * W_ + (4 * q - 4));
    }
    reinterpret_cast<float4*>(g_spad)[i] = v;
}

__global__ __launch_bounds__(480, 1)
void corr81_kernel(const float* __restrict__ first,
                   float* __restrict__ out) {
    const int h0  = 2 * blockIdx.x;    // output rows h0, h0+1
    const int b   = blockIdx.y;
    const int tid = threadIdx.x;       // 0..479
    const int pq  = tid % 48;
    const int g   = tid / 48;          // 0..9: second padded row = h0 + g
    const int w0  = 4 * pq;

    // set 0: output row h0, dy_pad = g      (store if g<=8)
    // set 1: output row h0+1, dy_pad = g-1  (store if g>=1)
    ull e0[5], a0[5], f0e[5], f0a[5];
    ull e1[5], a1[5], f1e[5], f1a[5];
#pragma unroll
    for (int m = 0; m < 5; m++) {
        e0[m]=0; a0[m]=0; f0e[m]=0; f0a[m]=0;
        e1[m]=0; a1[m]=0; f1e[m]=0; f1a[m]=0;
    }

    const float4* sp = reinterpret_cast<const float4*>(
        g_spad + ((size_t)(b * C_) * HP_ + (h0 + g)) * WP_ + w0);
    const float4* fp0 = reinterpret_cast<const float4*>(
        first + ((size_t)(b * C_) * H_ + h0) * W_ + w0);
    const float4* fp1 = fp0 + W_ / 4;

    // prologue: V for channel 0
    float4 V0 = sp[0], V1 = sp[1], V2 = sp[2];

    for (int c = 0; c < C_; c++) {
        // prefetch channel c+1's V (clamped on last iter: reload same, in-bounds)
        const int adv = (c < C_ - 1) ? 1 : 0;
        const float4* spn = sp + (size_t)adv * (HWP_ / 4);
        const float4 nV0 = spn[0];
        const float4 nV1 = spn[1];
        const float4 nV2 = spn[2];

        const float4 F0 = *fp0;
        const float4 F1 = *fp1;
        fp0 += HW_ / 4;
        fp1 += HW_ / 4;

        const ull E0 = lo_(V0.x, V0.y);
        const ull E1 = lo_(V0.z, V0.w);
        const ull E2 = lo_(V1.x, V1.y);
        const ull E3 = lo_(V1.z, V1.w);
        const ull E4 = lo_(V2.x, V2.y);
        const ull E5 = lo_(V2.z, V2.w);

        const ull p0a = lo_(F0.x, F0.y), p0b = lo_(F0.z, F0.w);
        const ull s0a = swap2(p0a),      s0b = swap2(p0b);
        const ull p1a = lo_(F1.x, F1.y), p1b = lo_(F1.z, F1.w);
        const ull s1a = swap2(p1a),      s1b = swap2(p1b);

        fma2(e0[0], p0a, E0);  fma2(a0[0], s0a, E0);
        fma2(e0[1], p0a, E1);  fma2(a0[1], s0a, E1);
        fma2(e0[2], p0a, E2);  fma2(a0[2], s0a, E2);
        fma2(e0[3], p0a, E3);  fma2(a0[3], s0a, E3);
        fma2(e0[4], p0a, E4);  fma2(a0[4], s0a, E4);
        fma2(f0e[0], p0b, E1); fma2(f0a[0], s0b, E1);
        fma2(f0e[1], p0b, E2); fma2(f0a[1], s0b, E2);
        fma2(f0e[2], p0b, E3); fma2(f0a[2], s0b, E3);
        fma2(f0e[3], p0b, E4); fma2(f0a[3], s0b, E4);
        fma2(f0e[4], p0b, E5); fma2(f0a[4], s0b, E5);

        fma2(e1[0], p1a, E0);  fma2(a1[0], s1a, E0);
        fma2(e1[1], p1a, E1);  fma2(a1[1], s1a, E1);
        fma2(e1[2], p1a, E2);  fma2(a1[2], s1a, E2);
        fma2(e1[3], p1a, E3);  fma2(a1[3], s1a, E3);
        fma2(e1[4], p1a, E4);  fma2(a1[4], s1a, E4);
        fma2(f1e[0], p1b, E1); fma2(f1a[0], s1b, E1);
        fma2(f1e[1], p1b, E2); fma2(f1a[1], s1b, E2);
        fma2(f1e[2], p1b, E3); fma2(f1a[2], s1b, E3);
        fma2(f1e[3], p1b, E4); fma2(f1a[3], s1b, E4);
        fma2(f1e[4], p1b, E5); fma2(f1a[4], s1b, E5);

        V0 = nV0; V1 = nV1; V2 = nV2;
        sp = spn;
    }

    const unsigned sb = __float_as_uint(1.0f / (float)C_);
    const ull scale2 = (ull)sb | ((ull)sb << 32);

    if (g <= 8) {   // set 0: channel g*9+dx at row h0
        float* od = out + (((size_t)(b * 81 + g * 9)) * H_ + h0) * W_ + w0;
#pragma unroll
        for (int m = 0; m < 5; m++) {
            ull va = e0[m];  mul2(va, scale2);
            ull vb = f0e[m]; mul2(vb, scale2);
            ulonglong2 pk; pk.x = va; pk.y = vb;
            *reinterpret_cast<ulonglong2*>(od + (size_t)(2 * m) * HW_) = pk;
        }
#pragma unroll
        for (int m = 0; m < 4; m++) {
            ull va = pack_hl(a0[m], a0[m + 1]); mul2(va, scale2);
            ull vb = pack_hl(f0a[m], f0a[m + 1]); mul2(vb, scale2);
            ulonglong2 pk; pk.x = va; pk.y = vb;
            *reinterpret_cast<ulonglong2*>(od + (size_t)(2 * m + 1) * HW_) = pk;
        }
    }
    if (g >= 1) {   // set 1: channel (g-1)*9+dx at row h0+1
        float* od = out + (((size_t)(b * 81 + (g - 1) * 9)) * H_ + (h0 + 1)) * W_ + w0;
#pragma unroll
        for (int m = 0; m < 5; m++) {
            ull va = e1[m];  mul2(va, scale2);
            ull vb = f1e[m]; mul2(vb, scale2);
            ulonglong2 pk; pk.x = va; pk.y = vb;
            *reinterpret_cast<ulonglong2*>(od + (size_t)(2 * m) * HW_) = pk;
        }
#pragma unroll
        for (int m = 0; m < 4; m++) {
            ull va = pack_hl(a1[m], a1[m + 1]); mul2(va, scale2);
            ull vb = pack_hl(f1a[m], f1a[m + 1]); mul2(vb, scale2);
            ulonglong2 pk; pk.x = va; pk.y = vb;
            *reinterpret_cast<ulonglong2*>(od + (size_t)(2 * m + 1) * HW_) = pk;
        }
    }
}

extern "C" void kernel_launch(void* const* d_in, const int* in_sizes, int n_in,
                              void* d_out, int out_size) {
    const float* first  = (const float*)d_in[0];
    const float* second = (const float*)d_in[1];
    float* out = (float*)d_out;

    const int pad_elems = B_ * C_ * HP_ * (WP_ / 4);
    pad_kernel<<<(pad_elems + 255) / 256, 256>>>(second);

    dim3 grid(H_ / 2, B_);   // (56, 8) h-pairs
    corr81_kernel<<<grid, 480>>>(first, out);
}